// round 15
// baseline (speedup 1.0000x reference)
#include <cuda_runtime.h>

#define BB 4
#define LL 1024
#define HH 8
#define BL (BB*LL)        // 4096
#define NBH (BB*HH)       // 32

typedef unsigned long long u64;

__device__ __forceinline__ float sqrt_approx(float x){ float y; asm("sqrt.approx.f32 %0, %1;" : "=f"(y) : "f"(x)); return y; }
__device__ __forceinline__ float ex2_approx (float x){ float y; asm("ex2.approx.f32 %0, %1;"  : "=f"(y) : "f"(x)); return y; }
__device__ __forceinline__ u64 pack2(float lo, float hi){ u64 r; asm("mov.b64 %0, {%1,%2};" : "=l"(r) : "f"(lo), "f"(hi)); return r; }
__device__ __forceinline__ float2 unpack2(u64 v){ float2 f; asm("mov.b64 {%0,%1}, %2;" : "=f"(f.x), "=f"(f.y) : "l"(v)); return f; }
__device__ __forceinline__ u64 fma2(u64 a, u64 b, u64 c){ u64 d; asm("fma.rn.f32x2 %0, %1, %2, %3;" : "=l"(d) : "l"(a), "l"(b), "l"(c)); return d; }
__device__ __forceinline__ u64 mul2(u64 a, u64 b){ u64 d; asm("mul.rn.f32x2 %0, %1, %2;" : "=l"(d) : "l"(a), "l"(b)); return d; }
__device__ __forceinline__ u64 add2(u64 a, u64 b){ u64 d; asm("add.rn.f32x2 %0, %1, %2;" : "=l"(d) : "l"(a), "l"(b)); return d; }

// -------- static scratch --------
__device__ float  g_WF  [512*120];          // fused W, k-major: [k][m*24+c]
__device__ float  g_XT  [512*BL];           // x transposed: [k][row]  (8 MB)
__device__ float  g_PS  [4*BL*120];         // GEMM partials [ks][row][col]
__device__ float  g_Rt  [BL*12];            // R (9) + t (3) per (b,l)
__device__ float4 g_QR  [NBH*LL];           // qr_g * wr2
__device__ float4 g_QD  [NBH*LL];           // qd_g * wd2
__device__ float  g_KEYC[NBH*9*LL];         // comp-major keys
__device__ float4 g_PART[NBH*LL*8];         // partial (a0,a1,a2,sum) per key-eighth

// ============ kernel 0: W-fuse + x-transpose (merged) ============
__global__ void __launch_bounds__(256) k_prep2(
    const float* __restrict__ x,
    const float* __restrict__ W0, const float* __restrict__ W1,
    const float* __restrict__ W2, const float* __restrict__ W3,
    const float* __restrict__ W4)
{
    int tid = threadIdx.x;
    if (blockIdx.x < 2048) {
        __shared__ float s[32][33];
        int r0 = (blockIdx.x >> 4) * 32;
        int c0 = (blockIdx.x & 15) * 32;
        {
            int rr = tid >> 3, cq = tid & 7;
            float4 v = *(const float4*)(x + (size_t)(r0+rr)*512 + c0 + cq*4);
            s[rr][cq*4+0] = v.x; s[rr][cq*4+1] = v.y;
            s[rr][cq*4+2] = v.z; s[rr][cq*4+3] = v.w;
        }
        __syncthreads();
        {
            int cc = tid >> 3, rq = tid & 7;
            float4 o = make_float4(s[rq*4+0][cc], s[rq*4+1][cc], s[rq*4+2][cc], s[rq*4+3][cc]);
            *(float4*)(g_XT + (size_t)(c0+cc)*BL + r0 + rq*4) = o;
        }
    } else {
        int bb = blockIdx.x - 2048;
        int m = bb / 8;
        int sl = bb % 8;
        const float* W;
        switch (m) {
            case 0: W=W0; break; case 1: W=W1; break; case 2: W=W2; break;
            case 3: W=W3; break; default: W=W4; break;
        }
        int base = sl * 1536;
        for (int i = base + tid; i < base + 1536; i += 256) {
            int k = i / 24, c = i % 24;
            g_WF[k*120 + m*24 + c] = W[i];
        }
    }
}

// ============ kernel 1: split-K GEMM (4 splits), f32x2 row-pair accumulate ============
__global__ void __launch_bounds__(512) k_gemm(
    const float* __restrict__ b0, const float* __restrict__ b1,
    const float* __restrict__ b2, const float* __restrict__ b3,
    const float* __restrict__ b4)
{
    __shared__ __align__(16) float sxk[64*36];    // x^T tile [k][row(32) pad 36]
    __shared__ __align__(16) float swk[64*120];   // W tile [k][col]
    int tid = threadIdx.x;
    int rt = blockIdx.x >> 2;
    int kc = blockIdx.x & 3;
    int row0 = rt * 32;

    bool act = tid < 480;
    int c  = tid % 120;
    int rg = tid / 120;             // rows rg*8 .. rg*8+7

    u64 acc2[4];
    {
        float bias = 0.f;
        if (kc == 0 && act) {
            int m = c / 24, cc = c % 24;
            const float* bv;
            switch (m) {
                case 0: bv=b0; break; case 1: bv=b1; break; case 2: bv=b2; break;
                case 3: bv=b3; break; default: bv=b4; break;
            }
            bias = __ldg(bv + cc);
        }
        u64 b2v = pack2(bias, bias);
        #pragma unroll
        for (int r=0;r<4;r++) acc2[r] = b2v;
    }

    #pragma unroll 1
    for (int phase=0; phase<2; phase++) {
        int k0 = kc*128 + phase*64;
        {
            int k = tid >> 3, rq = tid & 7;
            float4 v = *(const float4*)(g_XT + (size_t)(k0 + k)*BL + row0 + rq*4);
            *(float4*)(sxk + k*36 + rq*4) = v;
        }
        #pragma unroll
        for (int p=0; p<4; p++) {
            int lin = tid + p*512;
            if (lin < 1920)
                ((float4*)swk)[lin] = *(const float4*)(g_WF + k0*120 + lin*4);
        }
        __syncthreads();
        if (act) {
            const float* xb = sxk + rg*8;
            #pragma unroll 4
            for (int k=0; k<64; k++) {
                float w = swk[k*120 + c];
                u64 w2 = pack2(w, w);
                ulonglong2 xq0 = *(const ulonglong2*)(xb + k*36);      // rows 0-3 (2 pairs)
                ulonglong2 xq1 = *(const ulonglong2*)(xb + k*36 + 4);  // rows 4-7
                acc2[0] = fma2(xq0.x, w2, acc2[0]);
                acc2[1] = fma2(xq0.y, w2, acc2[1]);
                acc2[2] = fma2(xq1.x, w2, acc2[2]);
                acc2[3] = fma2(xq1.y, w2, acc2[3]);
            }
        }
        __syncthreads();
    }

    if (act) {
        float* ps = g_PS + ((size_t)kc*BL + row0 + rg*8)*120 + c;
        #pragma unroll
        for (int r=0;r<4;r++) {
            float2 v = unpack2(acc2[r]);
            ps[(2*r  )*120] = v.x;
            ps[(2*r+1)*120] = v.y;
        }
    }
}

// ============ kernel 2: combine 4 partials + frames + rotate/scale ============
__global__ void __launch_bounds__(256) k_comb(
    const float* __restrict__ coords, const int* __restrict__ cel,
    const int* __restrict__ mask,
    const float* __restrict__ w_r, const float* __restrict__ w_d)
{
    __shared__ __align__(16) float sres[8*120];
    __shared__ float sRt[8*12];
    __shared__ float sw2[2][HH];
    int tid  = threadIdx.x;
    int row0 = blockIdx.x * 8;

    if (tid < 8) {
        int gl = row0 + tid;
        const float* cp = coords + gl * 9;
        float nx=cp[0], ny=cp[1], nz=cp[2];
        float cax=cp[3], cay=cp[4], caz=cp[5];
        float cx=cp[6], cy=cp[7], cz=cp[8];
        float xx=cax-cx, xy=cay-cy, xz=caz-cz;
        float inv = 1.f / fmaxf(sqrtf(xx*xx + xy*xy + xz*xz), 1e-8f);
        xx*=inv; xy*=inv; xz*=inv;
        float yx=nx-cax, yy=ny-cay, yz=nz-caz;
        float d = xx*yx + xy*yy + xz*yz;
        yx -= d*xx; yy -= d*xy; yz -= d*xz;
        inv = 1.f / fmaxf(sqrtf(yx*yx + yy*yy + yz*yz), 1e-8f);
        yx*=inv; yy*=inv; yz*=inv;
        float zx = xy*yz - xz*yy;
        float zy = xz*yx - xx*yz;
        float zz = xx*yy - xy*yx;
        inv = 1.f / fmaxf(sqrtf(zx*zx + zy*zy + zz*zz), 1e-8f);
        zx*=inv; zy*=inv; zz*=inv;
        float R[12];
        if (cel[gl] != 0) {
            R[0]=xx; R[1]=xy; R[2]=xz; R[3]=yx; R[4]=yy; R[5]=yz;
            R[6]=zx; R[7]=zy; R[8]=zz; R[9]=cax; R[10]=cay; R[11]=caz;
        } else {
            R[0]=1.f;R[1]=0.f;R[2]=0.f; R[3]=0.f;R[4]=1.f;R[5]=0.f;
            R[6]=0.f;R[7]=0.f;R[8]=1.f; R[9]=0.f;R[10]=0.f;R[11]=0.f;
        }
        #pragma unroll
        for (int i=0;i<12;i++) { sRt[tid*12+i] = R[i]; g_Rt[gl*12+i] = R[i]; }
    } else if (tid < 16) {
        int h = tid - 8;
        const float C = 1.44269504088896f * 0.57735026918962f;  // log2e/sqrt3
        sw2[0][h] = log1pf(__expf(w_r[h])) * C;
        sw2[1][h] = log1pf(__expf(w_d[h])) * C;
    }

    if (tid < 240) {
        size_t base = (size_t)row0 * 120 + tid*4;
        float4 v0 = *(const float4*)(g_PS + 0*(size_t)BL*120 + base);
        float4 v1 = *(const float4*)(g_PS + 1*(size_t)BL*120 + base);
        float4 v2 = *(const float4*)(g_PS + 2*(size_t)BL*120 + base);
        float4 v3 = *(const float4*)(g_PS + 3*(size_t)BL*120 + base);
        float4 a;
        a.x = (v0.x + v1.x) + (v2.x + v3.x);
        a.y = (v0.y + v1.y) + (v2.y + v3.y);
        a.z = (v0.z + v1.z) + (v2.z + v3.z);
        a.w = (v0.w + v1.w) + (v2.w + v3.w);
        ((float4*)sres)[tid] = a;
    }
    __syncthreads();

    if (tid < 64) {
        int r = tid >> 3, h = tid & 7;
        int gl = row0 + r;
        float Rm[12];
        #pragma unroll
        for (int i=0;i<12;i++) Rm[i] = sRt[r*12+i];
        const float* rowv = &sres[r*120];
        int base = h*3;

        float qr0=rowv[ 0+base], qr1=rowv[ 1+base], qr2=rowv[ 2+base];
        float kr0=rowv[24+base], kr1=rowv[25+base], kr2=rowv[26+base];
        float qd0=rowv[48+base], qd1=rowv[49+base], qd2=rowv[50+base];
        float kd0=rowv[72+base], kd1=rowv[73+base], kd2=rowv[74+base];
        float vv0=rowv[96+base], vv1=rowv[97+base], vv2=rowv[98+base];

        #define ROT3(o0,o1,o2,a0,a1,a2)                          \
            o0 = a0*Rm[0] + a1*Rm[3] + a2*Rm[6];                 \
            o1 = a0*Rm[1] + a1*Rm[4] + a2*Rm[7];                 \
            o2 = a0*Rm[2] + a1*Rm[5] + a2*Rm[8];
        float qrg0,qrg1,qrg2, krg0,krg1,krg2, qdg0,qdg1,qdg2, kdg0,kdg1,kdg2, vg0,vg1,vg2;
        ROT3(qrg0,qrg1,qrg2, qr0,qr1,qr2);
        ROT3(krg0,krg1,krg2, kr0,kr1,kr2);
        ROT3(qdg0,qdg1,qdg2, qd0,qd1,qd2);
        ROT3(kdg0,kdg1,kdg2, kd0,kd1,kd2);
        ROT3(vg0, vg1, vg2,  vv0,vv1,vv2);
        #undef ROT3

        float wr2 = sw2[0][h], wd2 = sw2[1][h];
        qdg0 = (qdg0 + Rm[9]) * wd2; qdg1 = (qdg1 + Rm[10]) * wd2; qdg2 = (qdg2 + Rm[11]) * wd2;
        float kn0, kn1, kn2;
        if (mask[gl] == 0) { kn0 = kn1 = kn2 = -1e18f; }
        else {
            kn0 = -(kdg0 + Rm[9] ) * wd2;
            kn1 = -(kdg1 + Rm[10]) * wd2;
            kn2 = -(kdg2 + Rm[11]) * wd2;
        }
        qrg0 *= wr2; qrg1 *= wr2; qrg2 *= wr2;

        int b = gl >> 10, l = gl & 1023;
        int bh = b*HH + h;
        g_QR[bh*LL + l] = make_float4(qrg0, qrg1, qrg2, 0.f);
        g_QD[bh*LL + l] = make_float4(qdg0, qdg1, qdg2, 0.f);
        float* kc = g_KEYC + (size_t)(bh*9)*LL + l;
        kc[0*LL]=krg0; kc[1*LL]=krg1; kc[2*LL]=krg2;
        kc[3*LL]=kn0;  kc[4*LL]=kn1;  kc[5*LL]=kn2;
        kc[6*LL]=vg0;  kc[7*LL]=vg1;  kc[8*LL]=vg2;
    }
}

// ============ kernel 3: attention — 8-way key split for occupancy ============
// grid 2048 = bh(32) x qtile(8) x keighth(8); 128 threads; 128 keys in smem (4.5 KB)
__global__ void __launch_bounds__(128) k_attn()
{
    __shared__ __align__(16) float sK[9*128];   // 4.5 KB, comp-major
    int tid  = threadIdx.x;
    int kh   = blockIdx.x & 7;
    int tile = (blockIdx.x >> 3) & 7;
    int bh   = blockIdx.x >> 6;

    // load 128 keys x 9 comps = 288 float4
    #pragma unroll
    for (int i = tid; i < 288; i += 128) {
        int comp = i >> 5, pos = i & 31;
        ((float4*)sK)[i] =
            *(const float4*)(g_KEYC + (size_t)(bh*9 + comp)*LL + kh*128 + pos*4);
    }
    __syncthreads();

    int i = tile*128 + tid;
    int q = bh*LL + i;
    float4 QR = g_QR[q];
    float4 QD = g_QD[q];
    u64 qrx = pack2(QR.x, QR.x), qry = pack2(QR.y, QR.y), qrz = pack2(QR.z, QR.z);
    u64 qdx = pack2(QD.x, QD.x), qdy = pack2(QD.y, QD.y), qdz = pack2(QD.z, QD.z);

    const ulonglong2* KRX = (const ulonglong2*)(sK + 0*128);
    const ulonglong2* KRY = (const ulonglong2*)(sK + 1*128);
    const ulonglong2* KRZ = (const ulonglong2*)(sK + 2*128);
    const ulonglong2* KDX = (const ulonglong2*)(sK + 3*128);
    const ulonglong2* KDY = (const ulonglong2*)(sK + 4*128);
    const ulonglong2* KDZ = (const ulonglong2*)(sK + 5*128);
    const ulonglong2* VX  = (const ulonglong2*)(sK + 6*128);
    const ulonglong2* VY  = (const ulonglong2*)(sK + 7*128);
    const ulonglong2* VZ  = (const ulonglong2*)(sK + 8*128);

    u64 sum2 = 0ull, a0 = 0ull, a1 = 0ull, a2 = 0ull;

    #pragma unroll 4
    for (int jj=0; jj<32; jj++) {
        ulonglong2 krx = KRX[jj], kry = KRY[jj], krz = KRZ[jj];
        ulonglong2 kdx = KDX[jj], kdy = KDY[jj], kdz = KDZ[jj];
        ulonglong2 vx  = VX[jj],  vy  = VY[jj],  vz  = VZ[jj];
        {
            u64 dir = fma2(qrz, krz.x, fma2(qry, kry.x, mul2(qrx, krx.x)));
            u64 dx = add2(qdx, kdx.x);
            u64 dy = add2(qdy, kdy.x);
            u64 dz = add2(qdz, kdz.x);
            u64 d2 = fma2(dz, dz, fma2(dy, dy, mul2(dx, dx)));
            float2 d2f = unpack2(d2);
            float2 dirf = unpack2(dir);
            float p0 = ex2_approx(dirf.x - sqrt_approx(d2f.x));
            float p1 = ex2_approx(dirf.y - sqrt_approx(d2f.y));
            u64 p = pack2(p0, p1);
            sum2 = add2(sum2, p);
            a0 = fma2(p, vx.x, a0);
            a1 = fma2(p, vy.x, a1);
            a2 = fma2(p, vz.x, a2);
        }
        {
            u64 dir = fma2(qrz, krz.y, fma2(qry, kry.y, mul2(qrx, krx.y)));
            u64 dx = add2(qdx, kdx.y);
            u64 dy = add2(qdy, kdy.y);
            u64 dz = add2(qdz, kdz.y);
            u64 d2 = fma2(dz, dz, fma2(dy, dy, mul2(dx, dx)));
            float2 d2f = unpack2(d2);
            float2 dirf = unpack2(dir);
            float p0 = ex2_approx(dirf.x - sqrt_approx(d2f.x));
            float p1 = ex2_approx(dirf.y - sqrt_approx(d2f.y));
            u64 p = pack2(p0, p1);
            sum2 = add2(sum2, p);
            a0 = fma2(p, vx.y, a0);
            a1 = fma2(p, vy.y, a1);
            a2 = fma2(p, vz.y, a2);
        }
    }
    float2 s = unpack2(sum2), A0 = unpack2(a0), A1 = unpack2(a1), A2 = unpack2(a2);
    g_PART[q*8 + kh] = make_float4(A0.x+A0.y, A1.x+A1.y, A2.x+A2.y, s.x+s.y);
}

// ============ kernel 4: combine 8 partials + back-rotate + output projection ============
__global__ void __launch_bounds__(256) k_out(
    const float* __restrict__ Wp, const float* __restrict__ bp,
    const int* __restrict__ mask, float* __restrict__ out)
{
    __shared__ __align__(16) float so[16*24];
    __shared__ float smask[16];
    int tid = threadIdx.x;
    int gl0 = blockIdx.x * 16;

    if (tid < 128) {
        int r = tid >> 3, h = tid & 7;
        int gl = gl0 + r;
        int b = gl >> 10, l = gl & 1023;
        int q = (b*HH + h)*LL + l;
        float s0=0.f, s1=0.f, s2=0.f, sw=0.f;
        #pragma unroll
        for (int p=0; p<8; p++) {
            float4 pa = g_PART[q*8 + p];
            s0 += pa.x; s1 += pa.y; s2 += pa.z; sw += pa.w;
        }
        float inv = 1.f / sw;
        float o0 = s0 * inv, o1 = s1 * inv, o2 = s2 * inv;
        float Rm[9];
        #pragma unroll
        for (int i=0;i<9;i++) Rm[i] = g_Rt[gl*12 + i];
        so[r*24 + h*3 + 0] = o0*Rm[0] + o1*Rm[3] + o2*Rm[6];
        so[r*24 + h*3 + 1] = o0*Rm[1] + o1*Rm[4] + o2*Rm[7];
        so[r*24 + h*3 + 2] = o0*Rm[2] + o1*Rm[5] + o2*Rm[8];
        if (h == 0) smask[r] = (mask[gl] != 0) ? 1.f : 0.f;
    }
    __syncthreads();

    int c0 = tid, c1 = tid + 256;
    float wa[24], wb[24];
    #pragma unroll
    for (int f=0; f<24; f++) {
        wa[f] = __ldg(Wp + f*512 + c0);
        wb[f] = __ldg(Wp + f*512 + c1);
    }
    float ba = __ldg(bp + c0), bb_ = __ldg(bp + c1);

    for (int r=0; r<16; r++) {
        const float* o = &so[r*24];
        float aa = ba, ab = bb_;
        #pragma unroll
        for (int f=0; f<24; f++) {
            float ov = o[f];
            aa = fmaf(ov, wa[f], aa);
            ab = fmaf(ov, wb[f], ab);
        }
        float mf = smask[r];
        int gl = gl0 + r;
        out[(size_t)gl*512 + c0] = aa * mf;
        out[(size_t)gl*512 + c1] = ab * mf;
    }
}

// ================= launch =================
extern "C" void kernel_launch(void* const* d_in, const int* in_sizes, int n_in,
                              void* d_out, int out_size)
{
    const float* x      = (const float*)d_in[0];
    const float* coords = (const float*)d_in[1];
    const int* cel  = (const int*)d_in[2];
    const int* mask = (const int*)d_in[3];
    const float* Wqr = (const float*)d_in[4];  const float* bqr = (const float*)d_in[5];
    const float* Wkr = (const float*)d_in[6];  const float* bkr = (const float*)d_in[7];
    const float* Wqd = (const float*)d_in[8];  const float* bqd = (const float*)d_in[9];
    const float* Wkd = (const float*)d_in[10]; const float* bkd = (const float*)d_in[11];
    const float* Wv  = (const float*)d_in[12]; const float* bv  = (const float*)d_in[13];
    const float* w_r = (const float*)d_in[14]; const float* w_d = (const float*)d_in[15];
    const float* Wp  = (const float*)d_in[16]; const float* bp  = (const float*)d_in[17];

    k_prep2<<<2088, 256>>>(x, Wqr, Wkr, Wqd, Wkd, Wv);
    k_gemm <<<512, 512>>>(bqr, bkr, bqd, bkd, bv);
    k_comb <<<512, 256>>>(coords, cel, mask, w_r, w_d);
    k_attn <<<NBH*8*8, 128>>>();
    k_out  <<<256, 256>>>(Wp, bp, mask, (float*)d_out);
}

// round 16
// speedup vs baseline: 1.5243x; 1.5243x over previous
#include <cuda_runtime.h>

#define BB 4
#define LL 1024
#define HH 8
#define BL (BB*LL)        // 4096
#define NBH (BB*HH)       // 32

typedef unsigned long long u64;

__device__ __forceinline__ float sqrt_approx(float x){ float y; asm("sqrt.approx.f32 %0, %1;" : "=f"(y) : "f"(x)); return y; }
__device__ __forceinline__ float ex2_approx (float x){ float y; asm("ex2.approx.f32 %0, %1;"  : "=f"(y) : "f"(x)); return y; }
__device__ __forceinline__ u64 pack2(float lo, float hi){ u64 r; asm("mov.b64 %0, {%1,%2};" : "=l"(r) : "f"(lo), "f"(hi)); return r; }
__device__ __forceinline__ float2 unpack2(u64 v){ float2 f; asm("mov.b64 {%0,%1}, %2;" : "=f"(f.x), "=f"(f.y) : "l"(v)); return f; }
__device__ __forceinline__ u64 fma2(u64 a, u64 b, u64 c){ u64 d; asm("fma.rn.f32x2 %0, %1, %2, %3;" : "=l"(d) : "l"(a), "l"(b), "l"(c)); return d; }
__device__ __forceinline__ u64 mul2(u64 a, u64 b){ u64 d; asm("mul.rn.f32x2 %0, %1, %2;" : "=l"(d) : "l"(a), "l"(b)); return d; }
__device__ __forceinline__ u64 add2(u64 a, u64 b){ u64 d; asm("add.rn.f32x2 %0, %1, %2;" : "=l"(d) : "l"(a), "l"(b)); return d; }

// -------- static scratch --------
__device__ float  g_WF  [512*120];          // fused W, k-major: [k][m*24+c]
__device__ float  g_XT  [512*BL];           // x transposed: [k][row]  (8 MB)
__device__ float  g_PS  [4*BL*120];         // GEMM partials [ks][row][col]
__device__ float  g_Rt  [BL*12];            // R (9) + t (3) per (b,l)
__device__ float4 g_QR  [NBH*LL];           // qr_g * wr2
__device__ float4 g_QD  [NBH*LL];           // qd_g * wd2
__device__ float  g_KEYC[NBH*9*LL];         // comp-major keys
__device__ float4 g_PART[NBH*LL*4];         // partial (a0,a1,a2,sum) per key-quarter

// ============ kernel 0: W-fuse + x-transpose (merged) ============
__global__ void __launch_bounds__(256) k_prep2(
    const float* __restrict__ x,
    const float* __restrict__ W0, const float* __restrict__ W1,
    const float* __restrict__ W2, const float* __restrict__ W3,
    const float* __restrict__ W4)
{
    int tid = threadIdx.x;
    if (blockIdx.x < 2048) {
        __shared__ float s[32][33];
        int r0 = (blockIdx.x >> 4) * 32;
        int c0 = (blockIdx.x & 15) * 32;
        {
            int rr = tid >> 3, cq = tid & 7;
            float4 v = *(const float4*)(x + (size_t)(r0+rr)*512 + c0 + cq*4);
            s[rr][cq*4+0] = v.x; s[rr][cq*4+1] = v.y;
            s[rr][cq*4+2] = v.z; s[rr][cq*4+3] = v.w;
        }
        __syncthreads();
        {
            int cc = tid >> 3, rq = tid & 7;
            float4 o = make_float4(s[rq*4+0][cc], s[rq*4+1][cc], s[rq*4+2][cc], s[rq*4+3][cc]);
            *(float4*)(g_XT + (size_t)(c0+cc)*BL + r0 + rq*4) = o;
        }
    } else {
        int bb = blockIdx.x - 2048;
        int m = bb / 8;
        int sl = bb % 8;
        const float* W;
        switch (m) {
            case 0: W=W0; break; case 1: W=W1; break; case 2: W=W2; break;
            case 3: W=W3; break; default: W=W4; break;
        }
        int base = sl * 1536;
        for (int i = base + tid; i < base + 1536; i += 256) {
            int k = i / 24, c = i % 24;
            g_WF[k*120 + m*24 + c] = W[i];
        }
    }
}

// ============ kernel 1: split-K GEMM (4 splits), pressure-capped scalar FFMA ============
__global__ void __launch_bounds__(512) k_gemm(
    const float* __restrict__ b0, const float* __restrict__ b1,
    const float* __restrict__ b2, const float* __restrict__ b3,
    const float* __restrict__ b4)
{
    __shared__ __align__(16) float sxk[64*36];
    __shared__ __align__(16) float swk[64*120];
    int tid = threadIdx.x;
    int rt = blockIdx.x >> 2;
    int kc = blockIdx.x & 3;
    int row0 = rt * 32;

    bool act = tid < 480;
    int c  = tid % 120;
    int rg = tid / 120;

    float acc[8];
    {
        float bias = 0.f;
        if (kc == 0 && act) {
            int m = c / 24, cc = c % 24;
            const float* bv;
            switch (m) {
                case 0: bv=b0; break; case 1: bv=b1; break; case 2: bv=b2; break;
                case 3: bv=b3; break; default: bv=b4; break;
            }
            bias = __ldg(bv + cc);
        }
        #pragma unroll
        for (int r=0;r<8;r++) acc[r] = bias;
    }

    #pragma unroll 1
    for (int phase=0; phase<2; phase++) {
        int k0 = kc*128 + phase*64;
        {
            int k = tid >> 3, rq = tid & 7;
            float4 v = *(const float4*)(g_XT + (size_t)(k0 + k)*BL + row0 + rq*4);
            *(float4*)(sxk + k*36 + rq*4) = v;
        }
        #pragma unroll
        for (int p=0; p<4; p++) {
            int lin = tid + p*512;
            if (lin < 1920)
                ((float4*)swk)[lin] = *(const float4*)(g_WF + k0*120 + lin*4);
        }
        __syncthreads();
        if (act) {
            const float* xb = sxk + rg*8;
            #pragma unroll 4
            for (int k=0; k<64; k++) {
                float w = swk[k*120 + c];
                float4 xa = *(const float4*)(xb + k*36);
                float4 xc = *(const float4*)(xb + k*36 + 4);
                acc[0] = fmaf(xa.x, w, acc[0]);
                acc[1] = fmaf(xa.y, w, acc[1]);
                acc[2] = fmaf(xa.z, w, acc[2]);
                acc[3] = fmaf(xa.w, w, acc[3]);
                acc[4] = fmaf(xc.x, w, acc[4]);
                acc[5] = fmaf(xc.y, w, acc[5]);
                acc[6] = fmaf(xc.z, w, acc[6]);
                acc[7] = fmaf(xc.w, w, acc[7]);
            }
        }
        __syncthreads();
    }

    if (act) {
        float* ps = g_PS + ((size_t)kc*BL + row0 + rg*8)*120 + c;
        #pragma unroll
        for (int r=0;r<8;r++) ps[r*120] = acc[r];
    }
}

// ============ kernel 2: combine 4 partials + frames + rotate/scale ============
__global__ void __launch_bounds__(256) k_comb(
    const float* __restrict__ coords, const int* __restrict__ cel,
    const int* __restrict__ mask,
    const float* __restrict__ w_r, const float* __restrict__ w_d)
{
    __shared__ __align__(16) float sres[8*120];
    __shared__ float sRt[8*12];
    __shared__ float sw2[2][HH];
    int tid  = threadIdx.x;
    int row0 = blockIdx.x * 8;

    if (tid < 8) {
        int gl = row0 + tid;
        const float* cp = coords + gl * 9;
        float nx=cp[0], ny=cp[1], nz=cp[2];
        float cax=cp[3], cay=cp[4], caz=cp[5];
        float cx=cp[6], cy=cp[7], cz=cp[8];
        float xx=cax-cx, xy=cay-cy, xz=caz-cz;
        float inv = 1.f / fmaxf(sqrtf(xx*xx + xy*xy + xz*xz), 1e-8f);
        xx*=inv; xy*=inv; xz*=inv;
        float yx=nx-cax, yy=ny-cay, yz=nz-caz;
        float d = xx*yx + xy*yy + xz*yz;
        yx -= d*xx; yy -= d*xy; yz -= d*xz;
        inv = 1.f / fmaxf(sqrtf(yx*yx + yy*yy + yz*yz), 1e-8f);
        yx*=inv; yy*=inv; yz*=inv;
        float zx = xy*yz - xz*yy;
        float zy = xz*yx - xx*yz;
        float zz = xx*yy - xy*yx;
        inv = 1.f / fmaxf(sqrtf(zx*zx + zy*zy + zz*zz), 1e-8f);
        zx*=inv; zy*=inv; zz*=inv;
        float R[12];
        if (cel[gl] != 0) {
            R[0]=xx; R[1]=xy; R[2]=xz; R[3]=yx; R[4]=yy; R[5]=yz;
            R[6]=zx; R[7]=zy; R[8]=zz; R[9]=cax; R[10]=cay; R[11]=caz;
        } else {
            R[0]=1.f;R[1]=0.f;R[2]=0.f; R[3]=0.f;R[4]=1.f;R[5]=0.f;
            R[6]=0.f;R[7]=0.f;R[8]=1.f; R[9]=0.f;R[10]=0.f;R[11]=0.f;
        }
        #pragma unroll
        for (int i=0;i<12;i++) { sRt[tid*12+i] = R[i]; g_Rt[gl*12+i] = R[i]; }
    } else if (tid < 16) {
        int h = tid - 8;
        const float C = 1.44269504088896f * 0.57735026918962f;  // log2e/sqrt3
        sw2[0][h] = log1pf(__expf(w_r[h])) * C;
        sw2[1][h] = log1pf(__expf(w_d[h])) * C;
    }

    if (tid < 240) {
        size_t base = (size_t)row0 * 120 + tid*4;
        float4 v0 = *(const float4*)(g_PS + 0*(size_t)BL*120 + base);
        float4 v1 = *(const float4*)(g_PS + 1*(size_t)BL*120 + base);
        float4 v2 = *(const float4*)(g_PS + 2*(size_t)BL*120 + base);
        float4 v3 = *(const float4*)(g_PS + 3*(size_t)BL*120 + base);
        float4 a;
        a.x = (v0.x + v1.x) + (v2.x + v3.x);
        a.y = (v0.y + v1.y) + (v2.y + v3.y);
        a.z = (v0.z + v1.z) + (v2.z + v3.z);
        a.w = (v0.w + v1.w) + (v2.w + v3.w);
        ((float4*)sres)[tid] = a;
    }
    __syncthreads();

    if (tid < 64) {
        int r = tid >> 3, h = tid & 7;
        int gl = row0 + r;
        float Rm[12];
        #pragma unroll
        for (int i=0;i<12;i++) Rm[i] = sRt[r*12+i];
        const float* rowv = &sres[r*120];
        int base = h*3;

        float qr0=rowv[ 0+base], qr1=rowv[ 1+base], qr2=rowv[ 2+base];
        float kr0=rowv[24+base], kr1=rowv[25+base], kr2=rowv[26+base];
        float qd0=rowv[48+base], qd1=rowv[49+base], qd2=rowv[50+base];
        float kd0=rowv[72+base], kd1=rowv[73+base], kd2=rowv[74+base];
        float vv0=rowv[96+base], vv1=rowv[97+base], vv2=rowv[98+base];

        #define ROT3(o0,o1,o2,a0,a1,a2)                          \
            o0 = a0*Rm[0] + a1*Rm[3] + a2*Rm[6];                 \
            o1 = a0*Rm[1] + a1*Rm[4] + a2*Rm[7];                 \
            o2 = a0*Rm[2] + a1*Rm[5] + a2*Rm[8];
        float qrg0,qrg1,qrg2, krg0,krg1,krg2, qdg0,qdg1,qdg2, kdg0,kdg1,kdg2, vg0,vg1,vg2;
        ROT3(qrg0,qrg1,qrg2, qr0,qr1,qr2);
        ROT3(krg0,krg1,krg2, kr0,kr1,kr2);
        ROT3(qdg0,qdg1,qdg2, qd0,qd1,qd2);
        ROT3(kdg0,kdg1,kdg2, kd0,kd1,kd2);
        ROT3(vg0, vg1, vg2,  vv0,vv1,vv2);
        #undef ROT3

        float wr2 = sw2[0][h], wd2 = sw2[1][h];
        qdg0 = (qdg0 + Rm[9]) * wd2; qdg1 = (qdg1 + Rm[10]) * wd2; qdg2 = (qdg2 + Rm[11]) * wd2;
        float kn0, kn1, kn2;
        if (mask[gl] == 0) { kn0 = kn1 = kn2 = -1e18f; }
        else {
            kn0 = -(kdg0 + Rm[9] ) * wd2;
            kn1 = -(kdg1 + Rm[10]) * wd2;
            kn2 = -(kdg2 + Rm[11]) * wd2;
        }
        qrg0 *= wr2; qrg1 *= wr2; qrg2 *= wr2;

        int b = gl >> 10, l = gl & 1023;
        int bh = b*HH + h;
        g_QR[bh*LL + l] = make_float4(qrg0, qrg1, qrg2, 0.f);
        g_QD[bh*LL + l] = make_float4(qdg0, qdg1, qdg2, 0.f);
        float* kc = g_KEYC + (size_t)(bh*9)*LL + l;
        kc[0*LL]=krg0; kc[1*LL]=krg1; kc[2*LL]=krg2;
        kc[3*LL]=kn0;  kc[4*LL]=kn1;  kc[5*LL]=kn2;
        kc[6*LL]=vg0;  kc[7*LL]=vg1;  kc[8*LL]=vg2;
    }
}

// ============ kernel 3: attention — 4-way key split, 2 q-tiles per block ============
// grid 512 = bh(32) x qpair(4) x kquarter(4); 256 threads = 256 queries; 256 keys in smem
__global__ void __launch_bounds__(256) k_attn()
{
    __shared__ __align__(16) float sK[9*256];   // 9 KB, comp-major
    int tid  = threadIdx.x;
    int kh   = blockIdx.x & 3;
    int qp   = (blockIdx.x >> 2) & 3;
    int bh   = blockIdx.x >> 4;

    // load 256 keys x 9 comps = 576 float4 across 256 threads
    #pragma unroll
    for (int i = tid; i < 576; i += 256) {
        int comp = i >> 6, pos = i & 63;
        ((float4*)sK)[i] =
            *(const float4*)(g_KEYC + (size_t)(bh*9 + comp)*LL + kh*256 + pos*4);
    }
    __syncthreads();

    int i = qp*256 + tid;
    int q = bh*LL + i;
    float4 QR = g_QR[q];
    float4 QD = g_QD[q];
    u64 qrx = pack2(QR.x, QR.x), qry = pack2(QR.y, QR.y), qrz = pack2(QR.z, QR.z);
    u64 qdx = pack2(QD.x, QD.x), qdy = pack2(QD.y, QD.y), qdz = pack2(QD.z, QD.z);

    const ulonglong2* KRX = (const ulonglong2*)(sK + 0*256);
    const ulonglong2* KRY = (const ulonglong2*)(sK + 1*256);
    const ulonglong2* KRZ = (const ulonglong2*)(sK + 2*256);
    const ulonglong2* KDX = (const ulonglong2*)(sK + 3*256);
    const ulonglong2* KDY = (const ulonglong2*)(sK + 4*256);
    const ulonglong2* KDZ = (const ulonglong2*)(sK + 5*256);
    const ulonglong2* VX  = (const ulonglong2*)(sK + 6*256);
    const ulonglong2* VY  = (const ulonglong2*)(sK + 7*256);
    const ulonglong2* VZ  = (const ulonglong2*)(sK + 8*256);

    u64 sum2 = 0ull, a0 = 0ull, a1 = 0ull, a2 = 0ull;

    #pragma unroll 2
    for (int jj=0; jj<64; jj++) {
        ulonglong2 krx = KRX[jj], kry = KRY[jj], krz = KRZ[jj];
        ulonglong2 kdx = KDX[jj], kdy = KDY[jj], kdz = KDZ[jj];
        ulonglong2 vx  = VX[jj],  vy  = VY[jj],  vz  = VZ[jj];
        {
            u64 dir = fma2(qrz, krz.x, fma2(qry, kry.x, mul2(qrx, krx.x)));
            u64 dx = add2(qdx, kdx.x);
            u64 dy = add2(qdy, kdy.x);
            u64 dz = add2(qdz, kdz.x);
            u64 d2 = fma2(dz, dz, fma2(dy, dy, mul2(dx, dx)));
            float2 d2f = unpack2(d2);
            float2 dirf = unpack2(dir);
            float p0 = ex2_approx(dirf.x - sqrt_approx(d2f.x));
            float p1 = ex2_approx(dirf.y - sqrt_approx(d2f.y));
            u64 p = pack2(p0, p1);
            sum2 = add2(sum2, p);
            a0 = fma2(p, vx.x, a0);
            a1 = fma2(p, vy.x, a1);
            a2 = fma2(p, vz.x, a2);
        }
        {
            u64 dir = fma2(qrz, krz.y, fma2(qry, kry.y, mul2(qrx, krx.y)));
            u64 dx = add2(qdx, kdx.y);
            u64 dy = add2(qdy, kdy.y);
            u64 dz = add2(qdz, kdz.y);
            u64 d2 = fma2(dz, dz, fma2(dy, dy, mul2(dx, dx)));
            float2 d2f = unpack2(d2);
            float2 dirf = unpack2(dir);
            float p0 = ex2_approx(dirf.x - sqrt_approx(d2f.x));
            float p1 = ex2_approx(dirf.y - sqrt_approx(d2f.y));
            u64 p = pack2(p0, p1);
            sum2 = add2(sum2, p);
            a0 = fma2(p, vx.y, a0);
            a1 = fma2(p, vy.y, a1);
            a2 = fma2(p, vz.y, a2);
        }
    }
    float2 s = unpack2(sum2), A0 = unpack2(a0), A1 = unpack2(a1), A2 = unpack2(a2);
    g_PART[q*4 + kh] = make_float4(A0.x+A0.y, A1.x+A1.y, A2.x+A2.y, s.x+s.y);
}

// ============ kernel 4: combine 4 partials + back-rotate + output projection ============
__global__ void __launch_bounds__(256) k_out(
    const float* __restrict__ Wp, const float* __restrict__ bp,
    const int* __restrict__ mask, float* __restrict__ out)
{
    __shared__ __align__(16) float so[16*24];
    __shared__ float smask[16];
    int tid = threadIdx.x;
    int gl0 = blockIdx.x * 16;

    if (tid < 128) {
        int r = tid >> 3, h = tid & 7;
        int gl = gl0 + r;
        int b = gl >> 10, l = gl & 1023;
        int q = (b*HH + h)*LL + l;
        float4 pa = g_PART[q*4 + 0];
        float4 pb = g_PART[q*4 + 1];
        float4 pc = g_PART[q*4 + 2];
        float4 pd = g_PART[q*4 + 3];
        float ssum = (pa.w + pb.w) + (pc.w + pd.w);
        float inv = 1.f / ssum;
        float o0 = ((pa.x + pb.x) + (pc.x + pd.x)) * inv;
        float o1 = ((pa.y + pb.y) + (pc.y + pd.y)) * inv;
        float o2 = ((pa.z + pb.z) + (pc.z + pd.z)) * inv;
        float Rm[9];
        #pragma unroll
        for (int i=0;i<9;i++) Rm[i] = g_Rt[gl*12 + i];
        so[r*24 + h*3 + 0] = o0*Rm[0] + o1*Rm[3] + o2*Rm[6];
        so[r*24 + h*3 + 1] = o0*Rm[1] + o1*Rm[4] + o2*Rm[7];
        so[r*24 + h*3 + 2] = o0*Rm[2] + o1*Rm[5] + o2*Rm[8];
        if (h == 0) smask[r] = (mask[gl] != 0) ? 1.f : 0.f;
    }
    __syncthreads();

    int c0 = tid, c1 = tid + 256;
    float wa[24], wb[24];
    #pragma unroll
    for (int f=0; f<24; f++) {
        wa[f] = __ldg(Wp + f*512 + c0);
        wb[f] = __ldg(Wp + f*512 + c1);
    }
    float ba = __ldg(bp + c0), bb_ = __ldg(bp + c1);

    for (int r=0; r<16; r++) {
        const float* o = &so[r*24];
        float aa = ba, ab = bb_;
        #pragma unroll
        for (int f=0; f<24; f++) {
            float ov = o[f];
            aa = fmaf(ov, wa[f], aa);
            ab = fmaf(ov, wb[f], ab);
        }
        float mf = smask[r];
        int gl = gl0 + r;
        out[(size_t)gl*512 + c0] = aa * mf;
        out[(size_t)gl*512 + c1] = ab * mf;
    }
}

// ================= launch =================
extern "C" void kernel_launch(void* const* d_in, const int* in_sizes, int n_in,
                              void* d_out, int out_size)
{
    const float* x      = (const float*)d_in[0];
    const float* coords = (const float*)d_in[1];
    const int* cel  = (const int*)d_in[2];
    const int* mask = (const int*)d_in[3];
    const float* Wqr = (const float*)d_in[4];  const float* bqr = (const float*)d_in[5];
    const float* Wkr = (const float*)d_in[6];  const float* bkr = (const float*)d_in[7];
    const float* Wqd = (const float*)d_in[8];  const float* bqd = (const float*)d_in[9];
    const float* Wkd = (const float*)d_in[10]; const float* bkd = (const float*)d_in[11];
    const float* Wv  = (const float*)d_in[12]; const float* bv  = (const float*)d_in[13];
    const float* w_r = (const float*)d_in[14]; const float* w_d = (const float*)d_in[15];
    const float* Wp  = (const float*)d_in[16]; const float* bp  = (const float*)d_in[17];

    k_prep2<<<2088, 256>>>(x, Wqr, Wkr, Wqd, Wkd, Wv);
    k_gemm <<<512, 512>>>(bqr, bkr, bqd, bkd, bv);
    k_comb <<<512, 256>>>(coords, cel, mask, w_r, w_d);
    k_attn <<<NBH*4*4, 256>>>();
    k_out  <<<256, 256>>>(Wp, bp, mask, (float*)d_out);
}